// round 1
// baseline (speedup 1.0000x reference)
#include <cuda_runtime.h>
#include <cstdint>
#include <cub/cub.cuh>

// ---------------------------------------------------------------------------
// ProposalLayer: B=4, A=9, H=50, W=76, FEAT_STRIDE=16
// pre-NMS topN = 6000, post-NMS topN = 300, nms thresh = 0.7
// ---------------------------------------------------------------------------

#define BATCH     4
#define A_NUM     9
#define H_DIM     50
#define W_DIM     76
#define HW_DIM    (H_DIM * W_DIM)          // 3800
#define N_ANCH    (A_NUM * HW_DIM)         // 34200
#define PRE_TOPN  6000
#define POST_TOPN 300
#define NMS_TH    0.7f

// Precomputed generate_anchors(base=16, ratios={0.5,1,2}, scales={8,16,32})
__constant__ float c_anchors[A_NUM * 4] = {
    -84.f,  -40.f,   99.f,   55.f,
   -176.f,  -88.f,  191.f,  103.f,
   -360.f, -184.f,  375.f,  199.f,
    -56.f,  -56.f,   71.f,   71.f,
   -120.f, -120.f,  135.f,  135.f,
   -248.f, -248.f,  263.f,  263.f,
    -36.f,  -80.f,   51.f,   95.f,
    -80.f, -168.f,   95.f,  183.f,
   -168.f, -344.f,  183.f,  359.f
};

// Device-global scratch (no runtime allocation allowed)
__device__ unsigned long long g_keys_in [BATCH * N_ANCH];
__device__ unsigned long long g_keys_out[BATCH * N_ANCH];
__device__ float4             g_boxes   [BATCH * N_ANCH];
__device__ int                g_seg_off [BATCH + 1] =
    {0, N_ANCH, 2 * N_ANCH, 3 * N_ANCH, 4 * N_ANCH};
__device__ unsigned char      g_cub_temp[8 << 20];

// ---------------------------------------------------------------------------
// Kernel 1: decode + clip boxes, build 64-bit sort keys.
// Thread t -> (b, a, h, w) with w fastest => coalesced loads of scores/deltas.
// key = (score_bits << 32) | (0xFFFFFFFF - anchor_index)
//   descending sort => score desc, index asc  (matches stable argsort(-sc))
// ---------------------------------------------------------------------------
__global__ void decode_kernel(const float* __restrict__ scores,
                              const float* __restrict__ deltas,
                              const float* __restrict__ im_info)
{
    int t = blockIdx.x * blockDim.x + threadIdx.x;
    if (t >= BATCH * N_ANCH) return;

    int w  = t % W_DIM;
    int h  = (t / W_DIM) % H_DIM;
    int a  = (t / HW_DIM) % A_NUM;
    int b  = t / N_ANCH;
    int hw = h * W_DIM + w;

    float sx = (float)(w * 16);
    float sy = (float)(h * 16);
    float ax1 = c_anchors[a * 4 + 0] + sx;
    float ay1 = c_anchors[a * 4 + 1] + sy;
    float ax2 = c_anchors[a * 4 + 2] + sx;
    float ay2 = c_anchors[a * 4 + 3] + sy;

    float wa  = ax2 - ax1 + 1.0f;
    float ha  = ay2 - ay1 + 1.0f;
    float cxa = ax1 + 0.5f * wa;
    float cya = ay1 + 0.5f * ha;

    size_t dbase = ((size_t)b * 4 * A_NUM + (size_t)a * 4) * HW_DIM + hw;
    float dx = deltas[dbase];
    float dy = deltas[dbase +     HW_DIM];
    float dw = deltas[dbase + 2 * HW_DIM];
    float dh = deltas[dbase + 3 * HW_DIM];

    float pcx = dx * wa + cxa;
    float pcy = dy * ha + cya;
    float pw  = expf(dw) * wa;
    float ph  = expf(dh) * ha;

    float imh = im_info[b * 3 + 0];
    float imw = im_info[b * 3 + 1];

    float x1 = fminf(fmaxf(pcx - 0.5f * pw, 0.0f), imw - 1.0f);
    float y1 = fminf(fmaxf(pcy - 0.5f * ph, 0.0f), imh - 1.0f);
    float x2 = fminf(fmaxf(pcx + 0.5f * pw, 0.0f), imw - 1.0f);
    float y2 = fminf(fmaxf(pcy + 0.5f * ph, 0.0f), imh - 1.0f);

    int i = hw * A_NUM + a;   // reference flattening: ((h*W + w)*A + a)
    g_boxes[(size_t)b * N_ANCH + i] = make_float4(x1, y1, x2, y2);

    float sc = scores[((size_t)b * 2 * A_NUM + A_NUM + a) * HW_DIM + hw];
    g_keys_in[(size_t)b * N_ANCH + i] =
        ((unsigned long long)__float_as_uint(sc) << 32) |
        (unsigned long long)(0xFFFFFFFFu - (unsigned)i);
}

// ---------------------------------------------------------------------------
// Kernel 2: per-image greedy NMS over sorted top-6000, emit top-300 rows.
// One CTA per image; boxes/areas/alive flags resident in dynamic SMEM.
// ---------------------------------------------------------------------------
__global__ void nms_kernel(const unsigned long long* __restrict__ keys,
                           const float4* __restrict__ boxes_all,
                           float* __restrict__ out)
{
    int b = blockIdx.x;
    extern __shared__ unsigned char smem_raw[];
    float4*        boxes = (float4*)smem_raw;                    // 6000 * 16B
    float*         areas = (float*)(boxes + PRE_TOPN);           // 6000 * 4B
    unsigned char* alive = (unsigned char*)(areas + PRE_TOPN);   // 6000 * 1B
    __shared__ int s_next;

    const unsigned long long* k = keys + (size_t)b * N_ANCH;

    // Load top-6000 boxes (gather by decoded index), init areas + alive.
    for (int j = threadIdx.x; j < PRE_TOPN; j += blockDim.x) {
        unsigned idx = 0xFFFFFFFFu - (unsigned)(k[j] & 0xFFFFFFFFull);
        float4 v = boxes_all[(size_t)b * N_ANCH + idx];
        boxes[j] = v;
        areas[j] = (v.z - v.x + 1.0f) * (v.w - v.y + 1.0f);
        alive[j] = 1;
    }
    // Pre-fill output rows: [b, 0,0,0,0] (d_out arrives poisoned).
    for (int j = threadIdx.x; j < POST_TOPN; j += blockDim.x) {
        float* o = out + ((size_t)b * POST_TOPN + j) * 5;
        o[0] = (float)b;
        o[1] = 0.0f; o[2] = 0.0f; o[3] = 0.0f; o[4] = 0.0f;
    }
    __syncthreads();

    int count = 0;
    int cur   = 0;
    while (count < POST_TOPN) {
        // ---- find lowest alive index >= cur (parallel strided scan) ----
        if (threadIdx.x == 0) s_next = 0x7FFFFFFF;
        __syncthreads();
        for (int j = cur + threadIdx.x; j < PRE_TOPN; j += blockDim.x) {
            if (alive[j]) { atomicMin(&s_next, j); break; }
        }
        __syncthreads();
        int i = s_next;
        if (i == 0x7FFFFFFF) break;            // nothing left alive

        float4 bi = boxes[i];
        float  ai = areas[i];
        if (threadIdx.x == 0) {
            float* o = out + ((size_t)b * POST_TOPN + count) * 5;
            o[1] = bi.x; o[2] = bi.y; o[3] = bi.z; o[4] = bi.w;
        }
        count++;
        cur = i + 1;

        // ---- suppress overlapping boxes after i ----
        for (int j = cur + threadIdx.x; j < PRE_TOPN; j += blockDim.x) {
            if (alive[j]) {
                float4 bj = boxes[j];
                float iw = fminf(bi.z, bj.z) - fmaxf(bi.x, bj.x) + 1.0f;
                float ih = fminf(bi.w, bj.w) - fmaxf(bi.y, bj.y) + 1.0f;
                float inter = fmaxf(iw, 0.0f) * fmaxf(ih, 0.0f);
                float iou = inter / (ai + areas[j] - inter);
                if (iou > NMS_TH) alive[j] = 0;
            }
        }
        __syncthreads();
    }
}

// ---------------------------------------------------------------------------
// Launch
// ---------------------------------------------------------------------------
extern "C" void kernel_launch(void* const* d_in, const int* in_sizes, int n_in,
                              void* d_out, int out_size)
{
    const float* scores  = (const float*)d_in[0];   // (4, 18, 50, 76)
    const float* deltas  = (const float*)d_in[1];   // (4, 36, 50, 76)
    const float* im_info = (const float*)d_in[2];   // (4, 3)
    float*       out     = (float*)d_out;           // (4, 300, 5)

    void *keys_in_p, *keys_out_p, *boxes_p, *seg_p, *temp_p;
    cudaGetSymbolAddress(&keys_in_p,  g_keys_in);
    cudaGetSymbolAddress(&keys_out_p, g_keys_out);
    cudaGetSymbolAddress(&boxes_p,    g_boxes);
    cudaGetSymbolAddress(&seg_p,      g_seg_off);
    cudaGetSymbolAddress(&temp_p,     g_cub_temp);

    const int total = BATCH * N_ANCH;
    decode_kernel<<<(total + 255) / 256, 256>>>(scores, deltas, im_info);

    size_t temp_bytes = 0;
    cub::DeviceSegmentedRadixSort::SortKeysDescending(
        nullptr, temp_bytes,
        (const unsigned long long*)keys_in_p, (unsigned long long*)keys_out_p,
        total, BATCH, (const int*)seg_p, ((const int*)seg_p) + 1, 0, 64);
    if (temp_bytes > (size_t)(8 << 20)) temp_bytes = (size_t)(8 << 20);
    cub::DeviceSegmentedRadixSort::SortKeysDescending(
        temp_p, temp_bytes,
        (const unsigned long long*)keys_in_p, (unsigned long long*)keys_out_p,
        total, BATCH, (const int*)seg_p, ((const int*)seg_p) + 1, 0, 64);

    size_t smem = (size_t)PRE_TOPN * sizeof(float4)
                + (size_t)PRE_TOPN * sizeof(float)
                + (size_t)PRE_TOPN;                       // 126000 B
    cudaFuncSetAttribute(nms_kernel,
                         cudaFuncAttributeMaxDynamicSharedMemorySize,
                         (int)(smem + 1024));
    nms_kernel<<<BATCH, 256, smem>>>(
        (const unsigned long long*)keys_out_p, (const float4*)boxes_p, out);
}

// round 2
// speedup vs baseline: 4.9578x; 4.9578x over previous
#include <cuda_runtime.h>
#include <cstdint>
#include <cub/cub.cuh>

// ---------------------------------------------------------------------------
// ProposalLayer: B=4, A=9, H=50, W=76, FEAT_STRIDE=16
// pre-NMS topN = 6000, post-NMS topN = 300, nms thresh = 0.7
// ---------------------------------------------------------------------------

#define BATCH     4
#define A_NUM     9
#define H_DIM     50
#define W_DIM     76
#define HW_DIM    (H_DIM * W_DIM)          // 3800
#define N_ANCH    (A_NUM * HW_DIM)         // 34200
#define PRE_TOPN  6000
#define POST_TOPN 300
#define NMS_TH    0.7f
#define NWORDS    94                        // ceil(6000/64)
#define TAIL_BITS (PRE_TOPN - 64 * (NWORDS - 1))   // 48

// Precomputed generate_anchors(base=16, ratios={0.5,1,2}, scales={8,16,32})
__constant__ float c_anchors[A_NUM * 4] = {
    -84.f,  -40.f,   99.f,   55.f,
   -176.f,  -88.f,  191.f,  103.f,
   -360.f, -184.f,  375.f,  199.f,
    -56.f,  -56.f,   71.f,   71.f,
   -120.f, -120.f,  135.f,  135.f,
   -248.f, -248.f,  263.f,  263.f,
    -36.f,  -80.f,   51.f,   95.f,
    -80.f, -168.f,   95.f,  183.f,
   -168.f, -344.f,  183.f,  359.f
};

// Device-global scratch (no runtime allocation allowed)
__device__ unsigned long long g_keys_in [BATCH * N_ANCH];
__device__ unsigned long long g_keys_out[BATCH * N_ANCH];
__device__ float4             g_boxes   [BATCH * N_ANCH];
__device__ float4             g_sboxes  [BATCH][PRE_TOPN];
__device__ float              g_sareas  [BATCH][PRE_TOPN];
__device__ unsigned long long g_mask    [BATCH][PRE_TOPN][NWORDS];
__device__ int                g_seg_off [BATCH + 1] =
    {0, N_ANCH, 2 * N_ANCH, 3 * N_ANCH, 4 * N_ANCH};
__device__ unsigned char      g_cub_temp[8 << 20];

// ---------------------------------------------------------------------------
// Kernel 1: decode + clip boxes, build 64-bit sort keys.
// key = (score_bits << 32) | anchor_index. We radix-sort DESCENDING on bits
// [32,64) only; radix sort is stable, so equal scores keep index-ascending
// order == stable argsort(-sc).
// ---------------------------------------------------------------------------
__global__ void decode_kernel(const float* __restrict__ scores,
                              const float* __restrict__ deltas,
                              const float* __restrict__ im_info)
{
    int t = blockIdx.x * blockDim.x + threadIdx.x;
    if (t >= BATCH * N_ANCH) return;

    int w  = t % W_DIM;
    int h  = (t / W_DIM) % H_DIM;
    int a  = (t / HW_DIM) % A_NUM;
    int b  = t / N_ANCH;
    int hw = h * W_DIM + w;

    float sx = (float)(w * 16);
    float sy = (float)(h * 16);
    float ax1 = c_anchors[a * 4 + 0] + sx;
    float ay1 = c_anchors[a * 4 + 1] + sy;
    float ax2 = c_anchors[a * 4 + 2] + sx;
    float ay2 = c_anchors[a * 4 + 3] + sy;

    float wa  = ax2 - ax1 + 1.0f;
    float ha  = ay2 - ay1 + 1.0f;
    float cxa = ax1 + 0.5f * wa;
    float cya = ay1 + 0.5f * ha;

    size_t dbase = ((size_t)b * 4 * A_NUM + (size_t)a * 4) * HW_DIM + hw;
    float dx = deltas[dbase];
    float dy = deltas[dbase +     HW_DIM];
    float dw = deltas[dbase + 2 * HW_DIM];
    float dh = deltas[dbase + 3 * HW_DIM];

    float pcx = dx * wa + cxa;
    float pcy = dy * ha + cya;
    float pw  = expf(dw) * wa;
    float ph  = expf(dh) * ha;

    float imh = im_info[b * 3 + 0];
    float imw = im_info[b * 3 + 1];

    float x1 = fminf(fmaxf(pcx - 0.5f * pw, 0.0f), imw - 1.0f);
    float y1 = fminf(fmaxf(pcy - 0.5f * ph, 0.0f), imh - 1.0f);
    float x2 = fminf(fmaxf(pcx + 0.5f * pw, 0.0f), imw - 1.0f);
    float y2 = fminf(fmaxf(pcy + 0.5f * ph, 0.0f), imh - 1.0f);

    int i = hw * A_NUM + a;   // reference flattening: ((h*W + w)*A + a)
    g_boxes[(size_t)b * N_ANCH + i] = make_float4(x1, y1, x2, y2);

    float sc = scores[((size_t)b * 2 * A_NUM + A_NUM + a) * HW_DIM + hw];
    g_keys_in[(size_t)b * N_ANCH + i] =
        ((unsigned long long)__float_as_uint(sc) << 32) |
        (unsigned long long)(unsigned)i;
}

// ---------------------------------------------------------------------------
// Kernel 2: gather top-6000 sorted boxes + areas per image.
// ---------------------------------------------------------------------------
__global__ void gather_kernel(const unsigned long long* __restrict__ keys)
{
    int t = blockIdx.x * blockDim.x + threadIdx.x;
    if (t >= BATCH * PRE_TOPN) return;
    int b = t / PRE_TOPN;
    int j = t % PRE_TOPN;
    unsigned idx = (unsigned)(keys[(size_t)b * N_ANCH + j] & 0xFFFFFFFFull);
    float4 v = g_boxes[(size_t)b * N_ANCH + idx];
    g_sboxes[b][j] = v;
    g_sareas[b][j] = (v.z - v.x + 1.0f) * (v.w - v.y + 1.0f);
}

// ---------------------------------------------------------------------------
// Kernel 3: suppression bitmask matrix (upper triangle only).
// Block (bi, bj, b): 64 threads. Thread t owns row i = bi*64+t, computes the
// 64-bit word of columns [bj*64, bj*64+64) with bit c set iff IoU(i,j) > 0.7
// and j > i. Multiply-form test with guard band; exact division fallback only
// within 1e-5 relative distance of the threshold (decision-identical to ref).
// ---------------------------------------------------------------------------
__global__ void mask_kernel()
{
    int bi = blockIdx.x, bj = blockIdx.y, b = blockIdx.z;
    if (bj < bi) return;

    __shared__ float4 cb[64];
    __shared__ float  ca[64];
    int t  = threadIdx.x;
    int j0 = bj * 64;
    int jt = j0 + t;
    if (jt < PRE_TOPN) { cb[t] = g_sboxes[b][jt]; ca[t] = g_sareas[b][jt]; }
    __syncthreads();

    int i = bi * 64 + t;
    if (i >= PRE_TOPN) return;
    float4 bx = g_sboxes[b][i];
    float  ai = g_sareas[b][i];

    unsigned long long bits = 0;
    int cmax = min(64, PRE_TOPN - j0);
    #pragma unroll 4
    for (int c = 0; c < cmax; c++) {
        int j = j0 + c;
        if (j <= i) continue;
        float4 bv = cb[c];
        float iw = fminf(bx.z, bv.z) - fmaxf(bx.x, bv.x) + 1.0f;
        float ih = fminf(bx.w, bv.w) - fmaxf(bx.y, bv.y) + 1.0f;
        float inter = fmaxf(iw, 0.0f) * fmaxf(ih, 0.0f);
        float u  = ai + ca[c] - inter;
        float tq = NMS_TH * u;
        float diff = inter - tq;
        bool sup;
        if (fabsf(diff) > 1e-5f * u) sup = (diff > 0.0f);       // fast path
        else                         sup = (inter / u) > NMS_TH; // exact (rare)
        if (sup) bits |= (1ull << c);
    }
    g_mask[b][i][bj] = bits;
}

// ---------------------------------------------------------------------------
// Kernel 4: greedy reduce over the bitmask. One CTA per image, 128 threads.
// Sequential only in the number of KEPT boxes (~300), not candidates (6000).
// ---------------------------------------------------------------------------
__global__ void reduce_kernel(float* __restrict__ out)
{
    int b = blockIdx.x;
    int t = threadIdx.x;
    __shared__ unsigned long long s_rm[NWORDS];
    __shared__ int s_next;

    if (t < NWORDS) s_rm[t] = 0;
    // Pre-fill output rows: [b, 0,0,0,0]
    for (int j = t; j < POST_TOPN; j += blockDim.x) {
        float* o = out + ((size_t)b * POST_TOPN + j) * 5;
        o[0] = (float)b;
        o[1] = 0.0f; o[2] = 0.0f; o[3] = 0.0f; o[4] = 0.0f;
    }
    __syncthreads();

    int count = 0;
    int w = 0;
    unsigned long long passed = 0;
    while (count < POST_TOPN && w < NWORDS) {
        if (t == 0) {
            unsigned long long avail = ~(s_rm[w] | passed);
            if (w == NWORDS - 1) avail &= (1ull << TAIL_BITS) - 1;
            s_next = avail ? (w * 64 + __ffsll((long long)avail) - 1) : -1;
        }
        __syncthreads();
        int i = s_next;
        __syncthreads();
        if (i < 0) { w++; passed = 0; continue; }

        // OR kept row's suppression mask (only words >= i's word have bits)
        if (t < NWORDS && t >= (i >> 6)) s_rm[t] |= g_mask[b][i][t];
        if (t == 96) {
            float4 v = g_sboxes[b][i];
            float* o = out + ((size_t)b * POST_TOPN + count) * 5;
            o[1] = v.x; o[2] = v.y; o[3] = v.z; o[4] = v.w;
        }
        int bit = i & 63;
        passed |= (bit == 63) ? ~0ull : ((1ull << (bit + 1)) - 1);
        count++;
        __syncthreads();
    }
}

// ---------------------------------------------------------------------------
// Launch
// ---------------------------------------------------------------------------
extern "C" void kernel_launch(void* const* d_in, const int* in_sizes, int n_in,
                              void* d_out, int out_size)
{
    const float* scores  = (const float*)d_in[0];   // (4, 18, 50, 76)
    const float* deltas  = (const float*)d_in[1];   // (4, 36, 50, 76)
    const float* im_info = (const float*)d_in[2];   // (4, 3)
    float*       out     = (float*)d_out;           // (4, 300, 5)

    void *keys_in_p, *keys_out_p, *seg_p, *temp_p;
    cudaGetSymbolAddress(&keys_in_p,  g_keys_in);
    cudaGetSymbolAddress(&keys_out_p, g_keys_out);
    cudaGetSymbolAddress(&seg_p,      g_seg_off);
    cudaGetSymbolAddress(&temp_p,     g_cub_temp);

    const int total = BATCH * N_ANCH;
    decode_kernel<<<(total + 255) / 256, 256>>>(scores, deltas, im_info);

    // Sort only the score bits [32,64): stable radix keeps ties index-asc.
    size_t temp_bytes = 0;
    cub::DeviceSegmentedRadixSort::SortKeysDescending(
        nullptr, temp_bytes,
        (const unsigned long long*)keys_in_p, (unsigned long long*)keys_out_p,
        total, BATCH, (const int*)seg_p, ((const int*)seg_p) + 1, 32, 64);
    if (temp_bytes > (size_t)(8 << 20)) temp_bytes = (size_t)(8 << 20);
    cub::DeviceSegmentedRadixSort::SortKeysDescending(
        temp_p, temp_bytes,
        (const unsigned long long*)keys_in_p, (unsigned long long*)keys_out_p,
        total, BATCH, (const int*)seg_p, ((const int*)seg_p) + 1, 32, 64);

    gather_kernel<<<(BATCH * PRE_TOPN + 255) / 256, 256>>>(
        (const unsigned long long*)keys_out_p);

    dim3 mgrid(NWORDS, NWORDS, BATCH);
    mask_kernel<<<mgrid, 64>>>();

    reduce_kernel<<<BATCH, 128>>>(out);
}